// round 1
// baseline (speedup 1.0000x reference)
#include <cuda_runtime.h>
#include <cuda_bf16.h>
#include <math.h>

// Problem constants (PCVRSymbiosis): B=4, S=1024, L=1024, D=1024, H=16, HD=64, HIDDEN=4096
#define Bc 4
#define Sc 1024
#define Lc 1024
#define Dc 1024
#define Hc 16
#define HDc 64
#define HIDc 4096
#define BSc (Bc*Sc)
#define BLc (Bc*Lc)

// ---------------- scratch (static device globals; no runtime alloc) ----------------
__device__ float g_x    [BSc*Dc];
__device__ float g_qkv  [BSc*3*Dc];
__device__ float g_scores[(size_t)Bc*Hc*Sc*Sc];
__device__ float g_ctx  [BSc*Dc];
__device__ float g_t2   [BSc*Dc];
__device__ float g_qn   [BSc*Dc];
__device__ float g_sn   [BLc*Dc];
__device__ float g_cq   [BSc*Dc];
__device__ float g_ckv  [BLc*2*Dc];
__device__ float g_upd  [BSc*Dc];
__device__ float g_gacc [BSc*Dc];
__device__ float g_t3   [BSc*Dc];
__device__ float g_gu   [(size_t)BSc*2*HIDc];
__device__ float g_act  [(size_t)BSc*HIDc];
__device__ float g_ss   [Bc*2*Dc];
__device__ int   g_valid [BSc];
__device__ int   g_svalid[BLc];
__device__ float g_vrow  [Bc];
__device__ int   g_layout[2];   // zero-initialized at module load; updates are idempotent

// ---------------- reductions ----------------
__device__ __forceinline__ float warp_sum(float v){
    #pragma unroll
    for (int o=16;o>0;o>>=1) v += __shfl_xor_sync(0xffffffffu, v, o);
    return v;
}
__device__ __forceinline__ float warp_max(float v){
    #pragma unroll
    for (int o=16;o>0;o>>=1) v = fmaxf(v, __shfl_xor_sync(0xffffffffu, v, o));
    return v;
}
__device__ float block_sum(float v){
    __shared__ float red[33];
    __syncthreads();
    int lane = threadIdx.x & 31, wid = threadIdx.x >> 5;
    v = warp_sum(v);
    if (lane==0) red[wid] = v;
    __syncthreads();
    int nw = blockDim.x >> 5;
    float r = (threadIdx.x < nw) ? red[threadIdx.x] : 0.f;
    if (wid==0){ r = warp_sum(r); if (lane==0) red[32] = r; }
    __syncthreads();
    return red[32];
}
__device__ float block_max(float v){
    __shared__ float red[33];
    __syncthreads();
    int lane = threadIdx.x & 31, wid = threadIdx.x >> 5;
    v = warp_max(v);
    if (lane==0) red[wid] = v;
    __syncthreads();
    int nw = blockDim.x >> 5;
    float r = (threadIdx.x < nw) ? red[threadIdx.x] : -3.4e38f;
    if (wid==0){ r = warp_max(r); if (lane==0) red[32] = r; }
    __syncthreads();
    return red[32];
}

// ---------------- mask layout detection + decode ----------------
// Bool arrays may arrive as u8 (1B), int32, or float32. Scan the first `n`
// bytes (safe for all hypotheses: n = element count). Idempotent across calls.
__global__ void detect_mask_layout(const unsigned char* __restrict__ p, int n, int slot){
    int i = blockIdx.x*blockDim.x + threadIdx.x;
    if (i >= n) return;
    unsigned char v = p[i];
    if (v != 0 && v != 1) atomicOr(&g_layout[slot], 2);           // float32 (0x80/0x3f bytes)
    else if (v == 1 && (i & 3) != 0) atomicOr(&g_layout[slot], 1); // u8
}
// valid = ~mask, except all-pad rows become all-valid (safe_key_padding_mask).
// vrow[b] = any(~mask[b]) (pre-safe semantics), used for valid_rows gating.
__global__ void decode_mask(const void* __restrict__ p, int cols, int slot,
                            int* __restrict__ valid, float* __restrict__ vrow){
    int b = blockIdx.x;
    int layout = g_layout[slot];
    int mode = (layout & 2) ? 2 : ((layout & 1) ? 1 : 0);
    __shared__ int s_anyzero;
    if (threadIdx.x==0) s_anyzero = 0;
    __syncthreads();
    int local_any = 0;
    for (int j = threadIdx.x; j < cols; j += blockDim.x){
        long idx = (long)b*cols + j;
        int m;
        if (mode==1)      m = ((const unsigned char*)p)[idx] != 0;
        else if (mode==2) m = ((const float*)p)[idx] != 0.f;
        else              m = ((const int*)p)[idx] != 0;
        valid[idx] = m;
        if (!m) local_any = 1;
    }
    if (local_any) atomicOr(&s_anyzero, 1);
    __syncthreads();
    int anyz = s_anyzero;
    for (int j = threadIdx.x; j < cols; j += blockDim.x){
        long idx = (long)b*cols + j;
        valid[idx] = anyz ? (1 - valid[idx]) : 1;
    }
    if (vrow && threadIdx.x==0) vrow[b] = anyz ? 1.f : 0.f;
}

// ---------------- generic tiled GEMM: C = alpha * A @ op(B) + epilogue ----------------
// TRANSB=true:  B is [N,K] row-major (C[m,n] = sum_k A[m,k]*B[n,k])
// TRANSB=false: B is [K,N] row-major
// Batched via blockIdx.z decomposed as (z/batH, z%batH) with per-operand strides.
template<int BM,int BN,int BK,int TM,int TN,bool TRANSB>
__global__ __launch_bounds__((BM/TM)*(BN/TN))
void gemm_kernel(const float* __restrict__ A, const float* __restrict__ B,
                 float* __restrict__ C,
                 int M,int N,int K,int lda,int ldb,int ldc,
                 int batH,
                 long long aO,long long aI,long long bO,long long bI,
                 long long cO,long long cI,
                 float alpha,
                 const float* __restrict__ bias,
                 const float* __restrict__ residual,int ldres,
                 const float* __restrict__ rowscale,int rsDiv,
                 int accum)
{
    constexpr int NT = (BM/TM)*(BN/TN);
    const int tid = threadIdx.x;
    const int z = blockIdx.z;
    const float* Ab = A + (long long)(z/batH)*aO + (long long)(z%batH)*aI;
    const float* Bb = B + (long long)(z/batH)*bO + (long long)(z%batH)*bI;
    float*       Cb = C + (long long)(z/batH)*cO + (long long)(z%batH)*cI;

    __shared__ __align__(16) float As[BK][BM+4];
    __shared__ __align__(16) float Bs[BK][BN+4];

    const int m0 = blockIdx.y*BM, n0 = blockIdx.x*BN;
    const int tx = tid % (BN/TN), ty = tid / (BN/TN);

    float acc[TM][TN];
    #pragma unroll
    for (int i=0;i<TM;i++)
        #pragma unroll
        for (int j=0;j<TN;j++) acc[i][j]=0.f;

    for (int k0=0;k0<K;k0+=BK){
        constexpr int AIT = (BM*BK)/NT;
        #pragma unroll
        for (int it=0; it<AIT; ++it){
            int idx = tid + it*NT;
            int kl = idx % BK, ml = idx / BK;
            int gm = m0+ml, gk = k0+kl;
            As[kl][ml] = (gm<M && gk<K) ? Ab[(long long)gm*lda+gk] : 0.f;
        }
        constexpr int BIT = (BN*BK)/NT;
        if (TRANSB){
            #pragma unroll
            for (int it=0; it<BIT; ++it){
                int idx = tid + it*NT;
                int kl = idx % BK, nl = idx / BK;
                int gn = n0+nl, gk = k0+kl;
                Bs[kl][nl] = (gn<N && gk<K) ? Bb[(long long)gn*ldb+gk] : 0.f;
            }
        } else {
            #pragma unroll
            for (int it=0; it<BIT; ++it){
                int idx = tid + it*NT;
                int nl = idx % BN, kl = idx / BN;
                int gn = n0+nl, gk = k0+kl;
                Bs[kl][nl] = (gn<N && gk<K) ? Bb[(long long)gk*ldb+gn] : 0.f;
            }
        }
        __syncthreads();
        #pragma unroll
        for (int kk=0;kk<BK;kk++){
            float a[TM], b[TN];
            #pragma unroll
            for (int i=0;i<TM;i++) a[i]=As[kk][ty*TM+i];
            #pragma unroll
            for (int j=0;j<TN;j++) b[j]=Bs[kk][tx*TN+j];
            #pragma unroll
            for (int i=0;i<TM;i++)
                #pragma unroll
                for (int j=0;j<TN;j++)
                    acc[i][j] = fmaf(a[i], b[j], acc[i][j]);
        }
        __syncthreads();
    }
    #pragma unroll
    for (int i=0;i<TM;i++){
        int gm = m0 + ty*TM + i;
        if (gm>=M) continue;
        float rs = rowscale ? rowscale[gm/rsDiv] : 1.f;
        #pragma unroll
        for (int j=0;j<TN;j++){
            int gn = n0 + tx*TN + j;
            if (gn>=N) continue;
            float v = alpha*acc[i][j];
            if (bias) v += bias[gn];
            v *= rs;
            if (residual) v += residual[(long long)gm*(long long)ldres+gn];
            long long off = (long long)gm*ldc+gn;
            if (accum) v += Cb[off];
            Cb[off] = v;
        }
    }
}

// ---------------- small fused kernels ----------------
// FiLM gemv: out[b,n] = modulation[b,:] . film_w[n,:] + film_b[n]  (one warp per output)
__global__ void film_gemv(const float* __restrict__ mod, const float* __restrict__ W,
                          const float* __restrict__ bias, float* __restrict__ out,
                          int Bn, int N2, int K){
    int warp = (blockIdx.x*blockDim.x + threadIdx.x) >> 5;
    int lane = threadIdx.x & 31;
    if (warp >= Bn*N2) return;
    int b = warp / N2, n = warp % N2;
    const float* a = mod + (long)b*K;
    const float* w = W   + (long)n*K;
    float acc=0.f;
    for (int k=lane; k<K; k+=32) acc = fmaf(a[k], w[k], acc);
    acc = warp_sum(acc);
    if (lane==0) out[warp] = acc + bias[n];
}

// RMSNorm (+ optional FiLM): y = x * rsqrt(mean(x^2)+eps) * w [ * (1+0.1tanh(scale)) + shift ]
__global__ void rmsnorm_kernel(const float* __restrict__ x, const float* __restrict__ w,
                               float* __restrict__ y, int Dd,
                               const float* __restrict__ filmss, int S){
    long row = blockIdx.x;
    const float* xr = x + row*Dd;
    float ss = 0.f;
    for (int j = threadIdx.x; j < Dd; j += blockDim.x){ float v = xr[j]; ss = fmaf(v,v,ss); }
    ss = block_sum(ss);
    float r = rsqrtf(ss/(float)Dd + 1e-6f);
    if (filmss){
        int b = (int)(row / S);
        const float* sc = filmss + (long)b*2*Dd;
        for (int j = threadIdx.x; j < Dd; j += blockDim.x){
            float v = xr[j]*r*w[j];
            y[row*Dd + j] = v*(1.f + 0.1f*tanhf(sc[j])) + sc[Dd + j];
        }
    } else {
        for (int j = threadIdx.x; j < Dd; j += blockDim.x)
            y[row*Dd + j] = xr[j]*r*w[j];
    }
}

// RoPE in place on q (cols [0,D)) and k (cols [D,2D)) of qkv rows.
__global__ void rope_kernel(float* __restrict__ qkv){
    long idx = (long)blockIdx.x*blockDim.x + threadIdx.x;
    const long total = (long)BSc * Hc * (HDc/2);
    if (idx >= total) return;
    int i = idx % (HDc/2);
    int h = (idx / (HDc/2)) % Hc;
    long row = idx / ((HDc/2)*Hc);
    int s = (int)(row % Sc);
    float freq = expf(-logf(10000.f) * (float)(2*i) / (float)HDc);
    float ang = (float)s * freq;
    float c = cosf(ang), sn = sinf(ang);
    float* qb = qkv + row*(3*Dc) + h*HDc;
    float e = qb[2*i], o = qb[2*i+1];
    qb[2*i]   = e*c - o*sn;
    qb[2*i+1] = e*sn + o*c;
    float* kb = qb + Dc;
    e = kb[2*i]; o = kb[2*i+1];
    kb[2*i]   = e*c - o*sn;
    kb[2*i+1] = e*sn + o*c;
}

// masked softmax over rows of scores[z][q][cols]; valid indexed by b = z/H
__global__ void softmax_mask_kernel(float* __restrict__ scores, const int* __restrict__ valid,
                                    int cols, int Hh){
    int z = blockIdx.z;
    int b = z / Hh;
    float* row = scores + ((long long)z*gridDim.y + blockIdx.y)*cols;
    const int* vl = valid + (long)b*cols;
    float mx = -3.4e38f;
    for (int j=threadIdx.x; j<cols; j+=blockDim.x)
        if (vl[j]) mx = fmaxf(mx, row[j]);
    mx = block_max(mx);
    float sm = 0.f;
    for (int j=threadIdx.x; j<cols; j+=blockDim.x){
        float e = vl[j] ? expf(row[j]-mx) : 0.f;
        row[j] = e; sm += e;
    }
    sm = block_sum(sm);
    float inv = 1.f/sm;
    for (int j=threadIdx.x; j<cols; j+=blockDim.x) row[j] *= inv;
}

// t3 = t2 + sigmoid(gacc + gate_b) * upd
__global__ void gate_fuse_kernel(const float* __restrict__ t2, const float* __restrict__ gacc,
                                 const float* __restrict__ gate_b, const float* __restrict__ upd,
                                 float* __restrict__ t3, long n, int Dd){
    long i = (long)blockIdx.x*blockDim.x + threadIdx.x;
    if (i >= n) return;
    float g = gacc[i] + gate_b[i % Dd];
    float sg = 1.f / (1.f + expf(-g));
    t3[i] = t2[i] + sg * upd[i];
}

// act = silu(g) * val ; g = gu[:, :HID], val = gu[:, HID:]
__global__ void silu_kernel(const float* __restrict__ gu, float* __restrict__ act, long rows){
    long i = (long)blockIdx.x*blockDim.x + threadIdx.x;
    long n = rows * HIDc;
    if (i >= n) return;
    long m = i / HIDc; int j = (int)(i % HIDc);
    float g = gu[m*(2*HIDc) + j];
    float v = gu[m*(2*HIDc) + HIDc + j];
    float s = g / (1.f + expf(-g));
    act[i] = s * v;
}

// ---------------- host-side launch helpers ----------------
static inline void gemm_big_nt(const float* A,const float* B,float* C,
    int M,int N,int K,int lda,int ldb,int ldc,
    float alpha,const float* bias,const float* res,int ldres,
    const float* rs,int rsdiv,int accum,
    int zc=1,int batH=1,
    long long aO=0,long long aI=0,long long bO=0,long long bI=0,
    long long cO=0,long long cI=0)
{
    dim3 g((N+127)/128,(M+127)/128,zc);
    gemm_kernel<128,128,16,8,8,true><<<g,256>>>(A,B,C,M,N,K,lda,ldb,ldc,batH,
        aO,aI,bO,bI,cO,cI,alpha,bias,res,ldres,rs,rsdiv,accum);
}
static inline void gemm_small_nn(const float* A,const float* B,float* C,
    int M,int N,int K,int lda,int ldb,int ldc,
    float alpha,
    int zc,int batH,
    long long aO,long long aI,long long bO,long long bI,
    long long cO,long long cI)
{
    dim3 g((N+63)/64,(M+63)/64,zc);
    gemm_kernel<64,64,16,4,4,false><<<g,256>>>(A,B,C,M,N,K,lda,ldb,ldc,batH,
        aO,aI,bO,bI,cO,cI,alpha,nullptr,nullptr,0,nullptr,1,0);
}

extern "C" void kernel_launch(void* const* d_in, const int* in_sizes, int n_in,
                              void* d_out, int out_size)
{
    const float* tokens     = (const float*)d_in[0];
    const float* seq_tokens = (const float*)d_in[1];
    const float* modulation = (const float*)d_in[2];
    const float* attn_norm_w= (const float*)d_in[3];
    const float* qkv_w      = (const float*)d_in[4];
    const float* qkv_b      = (const float*)d_in[5];
    const float* out_w      = (const float*)d_in[6];
    const float* out_b      = (const float*)d_in[7];
    const float* film_w     = (const float*)d_in[8];
    const float* film_b     = (const float*)d_in[9];
    const float* sq_norm_w  = (const float*)d_in[10];
    const float* s_norm_w   = (const float*)d_in[11];
    const float* mha_in_w   = (const float*)d_in[12];
    const float* mha_in_b   = (const float*)d_in[13];
    const float* mha_out_w  = (const float*)d_in[14];
    const float* mha_out_b  = (const float*)d_in[15];
    const float* gate_w     = (const float*)d_in[16];
    const float* gate_b     = (const float*)d_in[17];
    const float* ffn_norm_w = (const float*)d_in[18];
    const float* gu_w       = (const float*)d_in[19];
    const float* gu_b       = (const float*)d_in[20];
    const float* down_w     = (const float*)d_in[21];
    const float* down_b     = (const float*)d_in[22];
    const void*  padding_mask = d_in[23];
    const void*  seq_mask     = d_in[24];
    float* out = (float*)d_out;

    float *p_x,*p_qkv,*p_scores,*p_ctx,*p_t2,*p_qn,*p_sn,*p_cq,*p_ckv,*p_upd,*p_gacc,*p_t3,*p_gu,*p_act,*p_ss,*p_vrow;
    int *p_valid,*p_svalid;
    cudaGetSymbolAddress((void**)&p_x, g_x);
    cudaGetSymbolAddress((void**)&p_qkv, g_qkv);
    cudaGetSymbolAddress((void**)&p_scores, g_scores);
    cudaGetSymbolAddress((void**)&p_ctx, g_ctx);
    cudaGetSymbolAddress((void**)&p_t2, g_t2);
    cudaGetSymbolAddress((void**)&p_qn, g_qn);
    cudaGetSymbolAddress((void**)&p_sn, g_sn);
    cudaGetSymbolAddress((void**)&p_cq, g_cq);
    cudaGetSymbolAddress((void**)&p_ckv, g_ckv);
    cudaGetSymbolAddress((void**)&p_upd, g_upd);
    cudaGetSymbolAddress((void**)&p_gacc, g_gacc);
    cudaGetSymbolAddress((void**)&p_t3, g_t3);
    cudaGetSymbolAddress((void**)&p_gu, g_gu);
    cudaGetSymbolAddress((void**)&p_act, g_act);
    cudaGetSymbolAddress((void**)&p_ss, g_ss);
    cudaGetSymbolAddress((void**)&p_vrow, g_vrow);
    cudaGetSymbolAddress((void**)&p_valid, g_valid);
    cudaGetSymbolAddress((void**)&p_svalid, g_svalid);

    const int BH = Bc*Hc;                     // 64
    const long long SS = (long long)Sc*Sc;    // 1M

    // 1) mask layout detect + decode
    detect_mask_layout<<<(Bc*Sc+255)/256,256>>>((const unsigned char*)padding_mask, Bc*Sc, 0);
    detect_mask_layout<<<(Bc*Lc+255)/256,256>>>((const unsigned char*)seq_mask,     Bc*Lc, 1);
    decode_mask<<<Bc,256>>>(padding_mask, Sc, 0, p_valid,  nullptr);
    decode_mask<<<Bc,256>>>(seq_mask,     Lc, 1, p_svalid, p_vrow);

    // 2) FiLM params: [B, 2D]
    film_gemv<<<(Bc*2*Dc*32 + 255)/256, 256>>>(modulation, film_w, film_b, p_ss, Bc, 2*Dc, Dc);

    // 3) x = FiLM(rmsnorm(tokens))
    rmsnorm_kernel<<<BSc,256>>>(tokens, attn_norm_w, p_x, Dc, p_ss, Sc);

    // 4) qkv = x @ qkv_w^T + qkv_b
    gemm_big_nt(p_x, qkv_w, p_qkv, BSc, 3*Dc, Dc, Dc, Dc, 3*Dc,
                1.f, qkv_b, nullptr, 0, nullptr, 1, 0);

    // 5) RoPE on q,k
    rope_kernel<<<((long)BSc*Hc*(HDc/2) + 255)/256, 256>>>(p_qkv);

    // 6) self-attn scores = (q @ k^T)/8, batched over (b,h)
    gemm_big_nt(p_qkv, p_qkv + Dc, p_scores, Sc, Sc, HDc, 3*Dc, 3*Dc, Sc,
                0.125f, nullptr, nullptr, 0, nullptr, 1, 0,
                BH, Hc,
                (long long)Sc*3*Dc, HDc, (long long)Sc*3*Dc, HDc,
                (long long)Hc*SS, SS);

    // 7) masked softmax
    { dim3 g(1, Sc, BH); softmax_mask_kernel<<<g,256>>>(p_scores, p_valid, Sc, Hc); }

    // 8) ctx = P @ V
    gemm_small_nn(p_scores, p_qkv + 2*Dc, p_ctx, Sc, HDc, Sc, Sc, 3*Dc, Dc,
                  1.f, BH, Hc,
                  (long long)Hc*SS, SS, (long long)Sc*3*Dc, HDc,
                  (long long)Sc*Dc, HDc);

    // 9) tokens2 = tokens + ctx @ out_w^T + out_b
    gemm_big_nt(p_ctx, out_w, p_t2, BSc, Dc, Dc, Dc, Dc, Dc,
                1.f, out_b, tokens, Dc, nullptr, 1, 0);

    // 10) query / src norms
    rmsnorm_kernel<<<BSc,256>>>(p_t2, sq_norm_w, p_qn, Dc, nullptr, Sc);
    rmsnorm_kernel<<<BLc,256>>>(seq_tokens, s_norm_w, p_sn, Dc, nullptr, Lc);

    // 11) cq = qn @ wq^T + bq ; ckv = sn @ [wk;wv]^T + [bk;bv]
    gemm_big_nt(p_qn, mha_in_w, p_cq, BSc, Dc, Dc, Dc, Dc, Dc,
                1.f, mha_in_b, nullptr, 0, nullptr, 1, 0);
    gemm_big_nt(p_sn, mha_in_w + (long long)Dc*Dc, p_ckv, BLc, 2*Dc, Dc, Dc, Dc, 2*Dc,
                1.f, mha_in_b + Dc, nullptr, 0, nullptr, 1, 0);

    // 12) cross scores = (cq @ ck^T)/8
    gemm_big_nt(p_cq, p_ckv, p_scores, Sc, Lc, HDc, Dc, 2*Dc, Lc,
                0.125f, nullptr, nullptr, 0, nullptr, 1, 0,
                BH, Hc,
                (long long)Sc*Dc, HDc, (long long)Lc*2*Dc, HDc,
                (long long)Hc*SS, SS);

    // 13) masked softmax (seq mask)
    { dim3 g(1, Sc, BH); softmax_mask_kernel<<<g,256>>>(p_scores, p_svalid, Lc, Hc); }

    // 14) ctx2 = P @ cv
    gemm_small_nn(p_scores, p_ckv + Dc, p_ctx, Sc, HDc, Lc, Lc, 2*Dc, Dc,
                  1.f, BH, Hc,
                  (long long)Hc*SS, SS, (long long)Lc*2*Dc, HDc,
                  (long long)Sc*Dc, HDc);

    // 15) update = (ctx2 @ mha_out_w^T + mha_out_b) * valid_rows[b]
    gemm_big_nt(p_ctx, mha_out_w, p_upd, BSc, Dc, Dc, Dc, Dc, Dc,
                1.f, mha_out_b, nullptr, 0, p_vrow, Sc, 0);

    // 16) gate pre-activation: gacc = t2 @ gate_w[:, :D]^T + upd @ gate_w[:, D:]^T
    gemm_big_nt(p_t2,  gate_w,      p_gacc, BSc, Dc, Dc, Dc, 2*Dc, Dc,
                1.f, nullptr, nullptr, 0, nullptr, 1, 0);
    gemm_big_nt(p_upd, gate_w + Dc, p_gacc, BSc, Dc, Dc, Dc, 2*Dc, Dc,
                1.f, nullptr, nullptr, 0, nullptr, 1, 1);

    // 17) t3 = t2 + sigmoid(gacc + gate_b) * upd
    gate_fuse_kernel<<<((long)BSc*Dc + 255)/256, 256>>>(p_t2, p_gacc, gate_b, p_upd, p_t3,
                                                        (long)BSc*Dc, Dc);

    // 18) h = rmsnorm(t3, ffn_norm_w) (reuse g_x)
    rmsnorm_kernel<<<BSc,256>>>(p_t3, ffn_norm_w, p_x, Dc, nullptr, Sc);

    // 19) gu = h @ gu_w^T + gu_b
    gemm_big_nt(p_x, gu_w, p_gu, BSc, 2*HIDc, Dc, Dc, Dc, 2*HIDc,
                1.f, gu_b, nullptr, 0, nullptr, 1, 0);

    // 20) act = silu(g) * val
    silu_kernel<<<((long)BSc*HIDc + 255)/256, 256>>>(p_gu, p_act, BSc);

    // 21) out = t3 + act @ down_w^T + down_b
    gemm_big_nt(p_act, down_w, out, BSc, Dc, HIDc, HIDc, HIDc, Dc,
                1.f, down_b, p_t3, Dc, nullptr, 1, 0);
}

// round 2
// speedup vs baseline: 2.0854x; 2.0854x over previous
#include <cuda_runtime.h>
#include <cuda_bf16.h>
#include <math.h>

// Problem constants (PCVRSymbiosis): B=4, S=1024, L=1024, D=1024, H=16, HD=64, HIDDEN=4096
#define Bc 4
#define Sc 1024
#define Lc 1024
#define Dc 1024
#define Hc 16
#define HDc 64
#define HIDc 4096
#define BSc (Bc*Sc)
#define BLc (Bc*Lc)

// ---------------- scratch (static device globals; no runtime alloc) ----------------
__device__ float g_x    [BSc*Dc];
__device__ float g_qkv  [BSc*3*Dc];
__device__ float g_scores[(size_t)Bc*Hc*Sc*Sc];
__device__ float g_ctx  [BSc*Dc];
__device__ float g_t2   [BSc*Dc];
__device__ float g_qn   [BSc*Dc];
__device__ float g_sn   [BLc*Dc];
__device__ float g_cq   [BSc*Dc];
__device__ float g_ckv  [BLc*2*Dc];
__device__ float g_upd  [BSc*Dc];
__device__ float g_gacc [BSc*Dc];
__device__ float g_t3   [BSc*Dc];
__device__ float g_gu   [(size_t)BSc*2*HIDc];
__device__ float g_act  [(size_t)BSc*HIDc];
__device__ float g_ss   [Bc*2*Dc];
__device__ int   g_valid [BSc];
__device__ int   g_svalid[BLc];
__device__ float g_vrow  [Bc];
__device__ int   g_layout[2];

// ---------------- reductions ----------------
__device__ __forceinline__ float warp_sum(float v){
    #pragma unroll
    for (int o=16;o>0;o>>=1) v += __shfl_xor_sync(0xffffffffu, v, o);
    return v;
}
__device__ __forceinline__ float warp_max(float v){
    #pragma unroll
    for (int o=16;o>0;o>>=1) v = fmaxf(v, __shfl_xor_sync(0xffffffffu, v, o));
    return v;
}
__device__ float block_sum(float v){
    __shared__ float red[33];
    __syncthreads();
    int lane = threadIdx.x & 31, wid = threadIdx.x >> 5;
    v = warp_sum(v);
    if (lane==0) red[wid] = v;
    __syncthreads();
    int nw = blockDim.x >> 5;
    float r = (threadIdx.x < nw) ? red[threadIdx.x] : 0.f;
    if (wid==0){ r = warp_sum(r); if (lane==0) red[32] = r; }
    __syncthreads();
    return red[32];
}
__device__ float block_max(float v){
    __shared__ float red[33];
    __syncthreads();
    int lane = threadIdx.x & 31, wid = threadIdx.x >> 5;
    v = warp_max(v);
    if (lane==0) red[wid] = v;
    __syncthreads();
    int nw = blockDim.x >> 5;
    float r = (threadIdx.x < nw) ? red[threadIdx.x] : -3.4e38f;
    if (wid==0){ r = warp_max(r); if (lane==0) red[32] = r; }
    __syncthreads();
    return red[32];
}

// ---------------- mask layout detection + decode (unchanged; proven correct) ----------------
__global__ void detect_mask_layout(const unsigned char* __restrict__ p, int n, int slot){
    int i = blockIdx.x*blockDim.x + threadIdx.x;
    if (i >= n) return;
    unsigned char v = p[i];
    if (v != 0 && v != 1) atomicOr(&g_layout[slot], 2);
    else if (v == 1 && (i & 3) != 0) atomicOr(&g_layout[slot], 1);
}
__global__ void decode_mask(const void* __restrict__ p, int cols, int slot,
                            int* __restrict__ valid, float* __restrict__ vrow){
    int b = blockIdx.x;
    int layout = g_layout[slot];
    int mode = (layout & 2) ? 2 : ((layout & 1) ? 1 : 0);
    __shared__ int s_anyzero;
    if (threadIdx.x==0) s_anyzero = 0;
    __syncthreads();
    int local_any = 0;
    for (int j = threadIdx.x; j < cols; j += blockDim.x){
        long idx = (long)b*cols + j;
        int m;
        if (mode==1)      m = ((const unsigned char*)p)[idx] != 0;
        else if (mode==2) m = ((const float*)p)[idx] != 0.f;
        else              m = ((const int*)p)[idx] != 0;
        valid[idx] = m;
        if (!m) local_any = 1;
    }
    if (local_any) atomicOr(&s_anyzero, 1);
    __syncthreads();
    int anyz = s_anyzero;
    for (int j = threadIdx.x; j < cols; j += blockDim.x){
        long idx = (long)b*cols + j;
        valid[idx] = anyz ? (1 - valid[idx]) : 1;
    }
    if (vrow && threadIdx.x==0) vrow[b] = anyz ? 1.f : 0.f;
}

// ---------------- tf32 helpers ----------------
__device__ __forceinline__ unsigned f2tf(float x){
    unsigned u; asm("cvt.rna.tf32.f32 %0, %1;" : "=r"(u) : "f"(x)); return u;
}
__device__ __forceinline__ void mma_tf32(float* c, const unsigned* a, const unsigned* b){
    asm volatile("mma.sync.aligned.m16n8k8.row.col.f32.tf32.tf32.f32 "
        "{%0,%1,%2,%3}, {%4,%5,%6,%7}, {%8,%9}, {%0,%1,%2,%3};"
        : "+f"(c[0]),"+f"(c[1]),"+f"(c[2]),"+f"(c[3])
        : "r"(a[0]),"r"(a[1]),"r"(a[2]),"r"(a[3]), "r"(b[0]),"r"(b[1]));
}

// ---------------- tf32 tensor-core GEMM: C = alpha * A @ op(B) + epilogue ----------------
// TRANSB=true : B is [N,K] row-major ; TRANSB=false : B is [K,N] row-major
// Shapes must divide evenly by (BM,BN,16) — true for all call sites here.
template<int BM,int BN,int NWM,int NWN,bool TRANSB>
__global__ __launch_bounds__(NWM*NWN*32)
void gemm_tc(const float* __restrict__ A, const float* __restrict__ B,
             float* __restrict__ C,
             int M,int N,int K,int lda,int ldb,int ldc,
             int batH,
             long long aO,long long aI,long long bO,long long bI,
             long long cO,long long cI,
             float alpha,
             const float* __restrict__ bias,
             const float* __restrict__ residual,int ldres,
             const float* __restrict__ rowscale,int rsDiv,
             int accum)
{
    constexpr int BK = 16;
    constexpr int NT = NWM*NWN*32;
    constexpr int WM = BM/NWM, WN = BN/NWN;
    constexpr int MI = WM/16, NI = WN/8;
    constexpr int LDA_S = BK+4;                       // As[m][k] stride (conflict-free frag reads)
    constexpr int LDB_S = TRANSB ? (BK+4) : (BN+8);
    constexpr int ASZ = BM*LDA_S;
    constexpr int BSZ = TRANSB ? BN*(BK+4) : BK*(BN+8);

    __shared__ unsigned As[ASZ];
    __shared__ unsigned Bs[BSZ];

    const int tid = threadIdx.x, lane = tid & 31, warp = tid >> 5;
    const int z = blockIdx.z;
    const float* Ab = A + (long long)(z/batH)*aO + (long long)(z%batH)*aI;
    const float* Bb = B + (long long)(z/batH)*bO + (long long)(z%batH)*bI;
    float*       Cb = C + (long long)(z/batH)*cO + (long long)(z%batH)*cI;

    const int m0 = blockIdx.y*BM, n0 = blockIdx.x*BN;
    const int wm0 = (warp/NWN)*WM, wn0 = (warp%NWN)*WN;
    const int qr = lane >> 2, qc = lane & 3;

    float acc[MI][NI][4];
    #pragma unroll
    for (int i=0;i<MI;i++)
        #pragma unroll
        for (int j=0;j<NI;j++)
            #pragma unroll
            for (int r=0;r<4;r++) acc[i][j][r]=0.f;

    constexpr int AF4 = (BM*BK)/(4*NT);
    constexpr int BF4 = (BN*BK)/(4*NT);
    float4 ra[AF4], rb[BF4];

    const int nk = K/BK;

    // prologue loads
    #pragma unroll
    for (int it=0; it<AF4; ++it){
        int idx = tid + it*NT; int m = idx>>2, kq = idx&3;
        ra[it] = *(const float4*)(Ab + (long long)(m0+m)*lda + kq*4);
    }
    #pragma unroll
    for (int it=0; it<BF4; ++it){
        int idx = tid + it*NT;
        if (TRANSB){ int n = idx>>2, kq = idx&3;
            rb[it] = *(const float4*)(Bb + (long long)(n0+n)*ldb + kq*4);
        } else { int kl = idx/(BN/4), nq = idx%(BN/4);
            rb[it] = *(const float4*)(Bb + (long long)kl*ldb + n0 + nq*4);
        }
    }

    for (int kt=0; kt<nk; ++kt){
        __syncthreads();
        // stage regs -> smem (converted to tf32)
        #pragma unroll
        for (int it=0; it<AF4; ++it){
            int idx = tid + it*NT; int m = idx>>2, kq = idx&3;
            unsigned* d = &As[m*LDA_S + kq*4];
            d[0]=f2tf(ra[it].x); d[1]=f2tf(ra[it].y); d[2]=f2tf(ra[it].z); d[3]=f2tf(ra[it].w);
        }
        #pragma unroll
        for (int it=0; it<BF4; ++it){
            int idx = tid + it*NT;
            unsigned* d;
            if (TRANSB){ int n = idx>>2, kq = idx&3; d = &Bs[n*LDB_S + kq*4]; }
            else       { int kl = idx/(BN/4), nq = idx%(BN/4); d = &Bs[kl*LDB_S + nq*4]; }
            d[0]=f2tf(rb[it].x); d[1]=f2tf(rb[it].y); d[2]=f2tf(rb[it].z); d[3]=f2tf(rb[it].w);
        }
        __syncthreads();
        // prefetch next tile into registers (overlaps with mma below)
        if (kt+1 < nk){
            int k0 = (kt+1)*BK;
            #pragma unroll
            for (int it=0; it<AF4; ++it){
                int idx = tid + it*NT; int m = idx>>2, kq = idx&3;
                ra[it] = *(const float4*)(Ab + (long long)(m0+m)*lda + k0 + kq*4);
            }
            #pragma unroll
            for (int it=0; it<BF4; ++it){
                int idx = tid + it*NT;
                if (TRANSB){ int n = idx>>2, kq = idx&3;
                    rb[it] = *(const float4*)(Bb + (long long)(n0+n)*ldb + k0 + kq*4);
                } else { int kl = idx/(BN/4), nq = idx%(BN/4);
                    rb[it] = *(const float4*)(Bb + (long long)(k0+kl)*ldb + n0 + nq*4);
                }
            }
        }
        // compute: 2 k-steps of 8
        #pragma unroll
        for (int ks=0; ks<BK; ks+=8){
            unsigned af[MI][4], bf[NI][2];
            #pragma unroll
            for (int mi=0; mi<MI; ++mi){
                int mr = wm0 + mi*16 + qr;
                af[mi][0] = As[ mr   *LDA_S + ks+qc  ];
                af[mi][1] = As[(mr+8)*LDA_S + ks+qc  ];
                af[mi][2] = As[ mr   *LDA_S + ks+qc+4];
                af[mi][3] = As[(mr+8)*LDA_S + ks+qc+4];
            }
            #pragma unroll
            for (int ni=0; ni<NI; ++ni){
                int nc = wn0 + ni*8 + qr;
                if (TRANSB){
                    bf[ni][0] = Bs[nc*LDB_S + ks+qc  ];
                    bf[ni][1] = Bs[nc*LDB_S + ks+qc+4];
                } else {
                    bf[ni][0] = Bs[(ks+qc  )*LDB_S + nc];
                    bf[ni][1] = Bs[(ks+qc+4)*LDB_S + nc];
                }
            }
            #pragma unroll
            for (int mi=0; mi<MI; ++mi)
                #pragma unroll
                for (int ni=0; ni<NI; ++ni)
                    mma_tf32(acc[mi][ni], af[mi], bf[ni]);
        }
    }

    // epilogue
    #pragma unroll
    for (int mi=0; mi<MI; ++mi){
        #pragma unroll
        for (int half=0; half<2; ++half){
            int gm = m0 + wm0 + mi*16 + qr + half*8;
            float rs = rowscale ? rowscale[gm/rsDiv] : 1.f;
            #pragma unroll
            for (int ni=0; ni<NI; ++ni){
                int gn = n0 + wn0 + ni*8 + qc*2;
                float v0 = alpha*acc[mi][ni][half*2+0];
                float v1 = alpha*acc[mi][ni][half*2+1];
                if (bias){ v0 += bias[gn]; v1 += bias[gn+1]; }
                v0 *= rs; v1 *= rs;
                if (residual){
                    float2 r = *(const float2*)(residual + (long long)gm*ldres + gn);
                    v0 += r.x; v1 += r.y;
                }
                long long off = (long long)gm*ldc + gn;
                if (accum){ float2 c0 = *(float2*)(Cb+off); v0 += c0.x; v1 += c0.y; }
                *(float2*)(Cb+off) = make_float2(v0, v1);
            }
        }
    }
}

// ---------------- small fused kernels ----------------
__global__ void film_gemv(const float* __restrict__ mod, const float* __restrict__ W,
                          const float* __restrict__ bias, float* __restrict__ out,
                          int Bn, int N2, int K){
    int warp = (blockIdx.x*blockDim.x + threadIdx.x) >> 5;
    int lane = threadIdx.x & 31;
    if (warp >= Bn*N2) return;
    int b = warp / N2, n = warp % N2;
    const float* a = mod + (long)b*K;
    const float* w = W   + (long)n*K;
    float acc=0.f;
    for (int k=lane; k<K; k+=32) acc = fmaf(a[k], w[k], acc);
    acc = warp_sum(acc);
    if (lane==0) out[warp] = acc + bias[n];
}

__global__ void rmsnorm_kernel(const float* __restrict__ x, const float* __restrict__ w,
                               float* __restrict__ y, int Dd,
                               const float* __restrict__ filmss, int S){
    long row = blockIdx.x;
    const float* xr = x + row*Dd;
    float ss = 0.f;
    for (int j = threadIdx.x; j < Dd; j += blockDim.x){ float v = xr[j]; ss = fmaf(v,v,ss); }
    ss = block_sum(ss);
    float r = rsqrtf(ss/(float)Dd + 1e-6f);
    if (filmss){
        int b = (int)(row / S);
        const float* sc = filmss + (long)b*2*Dd;
        for (int j = threadIdx.x; j < Dd; j += blockDim.x){
            float v = xr[j]*r*w[j];
            y[row*Dd + j] = v*(1.f + 0.1f*tanhf(sc[j])) + sc[Dd + j];
        }
    } else {
        for (int j = threadIdx.x; j < Dd; j += blockDim.x)
            y[row*Dd + j] = xr[j]*r*w[j];
    }
}

__global__ void rope_kernel(float* __restrict__ qkv){
    long idx = (long)blockIdx.x*blockDim.x + threadIdx.x;
    const long total = (long)BSc * Hc * (HDc/2);
    if (idx >= total) return;
    int i = idx % (HDc/2);
    int h = (idx / (HDc/2)) % Hc;
    long row = idx / ((HDc/2)*Hc);
    int s = (int)(row % Sc);
    float freq = expf(-logf(10000.f) * (float)(2*i) / (float)HDc);
    float ang = (float)s * freq;
    float c = cosf(ang), sn = sinf(ang);
    float* qb = qkv + row*(3*Dc) + h*HDc;
    float e = qb[2*i], o = qb[2*i+1];
    qb[2*i]   = e*c - o*sn;
    qb[2*i+1] = e*sn + o*c;
    float* kb = qb + Dc;
    e = kb[2*i]; o = kb[2*i+1];
    kb[2*i]   = e*c - o*sn;
    kb[2*i+1] = e*sn + o*c;
}

// masked softmax, row cached in smem: 1 global read + 1 global write per row
__global__ void softmax_mask_kernel(float* __restrict__ scores, const int* __restrict__ valid,
                                    int cols, int Hh){
    __shared__ float buf[1024];
    int z = blockIdx.z;
    int b = z / Hh;
    float* row = scores + ((long long)z*gridDim.y + blockIdx.y)*cols;
    const int* vl = valid + (long)b*cols;
    float mx = -3.4e38f;
    for (int j=threadIdx.x; j<cols; j+=blockDim.x){
        float v = vl[j] ? row[j] : -3.4e38f;
        buf[j] = v;
        mx = fmaxf(mx, v);
    }
    mx = block_max(mx);
    float sm = 0.f;
    for (int j=threadIdx.x; j<cols; j+=blockDim.x){
        float e = expf(buf[j]-mx);
        buf[j] = e; sm += e;
    }
    sm = block_sum(sm);
    float inv = 1.f/sm;
    for (int j=threadIdx.x; j<cols; j+=blockDim.x) row[j] = buf[j]*inv;
}

__global__ void gate_fuse_kernel(const float* __restrict__ t2, const float* __restrict__ gacc,
                                 const float* __restrict__ gate_b, const float* __restrict__ upd,
                                 float* __restrict__ t3, long n, int Dd){
    long i = (long)blockIdx.x*blockDim.x + threadIdx.x;
    if (i >= n) return;
    float g = gacc[i] + gate_b[i % Dd];
    float sg = 1.f / (1.f + expf(-g));
    t3[i] = t2[i] + sg * upd[i];
}

__global__ void silu_kernel(const float* __restrict__ gu, float* __restrict__ act, long rows){
    long i = (long)blockIdx.x*blockDim.x + threadIdx.x;
    long n = rows * HIDc;
    if (i >= n) return;
    long m = i / HIDc; int j = (int)(i % HIDc);
    float g = gu[m*(2*HIDc) + j];
    float v = gu[m*(2*HIDc) + HIDc + j];
    float s = g / (1.f + expf(-g));
    act[i] = s * v;
}

// ---------------- host-side launch helpers ----------------
static inline void tc_nt(const float* A,const float* B,float* C,
    int M,int N,int K,int lda,int ldb,int ldc,
    float alpha,const float* bias,const float* res,int ldres,
    const float* rs,int rsdiv,int accum,
    int zc=1,int batH=1,
    long long aO=0,long long aI=0,long long bO=0,long long bI=0,
    long long cO=0,long long cI=0)
{
    dim3 g(N/128, M/128, zc);
    gemm_tc<128,128,2,4,true><<<g,256>>>(A,B,C,M,N,K,lda,ldb,ldc,batH,
        aO,aI,bO,bI,cO,cI,alpha,bias,res,ldres,rs,rsdiv,accum);
}
static inline void tc_nn_pv(const float* A,const float* B,float* C,
    int M,int N,int K,int lda,int ldb,int ldc,
    int zc,int batH,
    long long aO,long long aI,long long bO,long long bI,
    long long cO,long long cI)
{
    dim3 g(N/64, M/128, zc);
    gemm_tc<128,64,4,2,false><<<g,256>>>(A,B,C,M,N,K,lda,ldb,ldc,batH,
        aO,aI,bO,bI,cO,cI,1.f,nullptr,nullptr,0,nullptr,1,0);
}

extern "C" void kernel_launch(void* const* d_in, const int* in_sizes, int n_in,
                              void* d_out, int out_size)
{
    const float* tokens     = (const float*)d_in[0];
    const float* seq_tokens = (const float*)d_in[1];
    const float* modulation = (const float*)d_in[2];
    const float* attn_norm_w= (const float*)d_in[3];
    const float* qkv_w      = (const float*)d_in[4];
    const float* qkv_b      = (const float*)d_in[5];
    const float* out_w      = (const float*)d_in[6];
    const float* out_b      = (const float*)d_in[7];
    const float* film_w     = (const float*)d_in[8];
    const float* film_b     = (const float*)d_in[9];
    const float* sq_norm_w  = (const float*)d_in[10];
    const float* s_norm_w   = (const float*)d_in[11];
    const float* mha_in_w   = (const float*)d_in[12];
    const float* mha_in_b   = (const float*)d_in[13];
    const float* mha_out_w  = (const float*)d_in[14];
    const float* mha_out_b  = (const float*)d_in[15];
    const float* gate_w     = (const float*)d_in[16];
    const float* gate_b     = (const float*)d_in[17];
    const float* ffn_norm_w = (const float*)d_in[18];
    const float* gu_w       = (const float*)d_in[19];
    const float* gu_b       = (const float*)d_in[20];
    const float* down_w     = (const float*)d_in[21];
    const float* down_b     = (const float*)d_in[22];
    const void*  padding_mask = d_in[23];
    const void*  seq_mask     = d_in[24];
    float* out = (float*)d_out;

    float *p_x,*p_qkv,*p_scores,*p_ctx,*p_t2,*p_qn,*p_sn,*p_cq,*p_ckv,*p_upd,*p_gacc,*p_t3,*p_gu,*p_act,*p_ss,*p_vrow;
    int *p_valid,*p_svalid;
    cudaGetSymbolAddress((void**)&p_x, g_x);
    cudaGetSymbolAddress((void**)&p_qkv, g_qkv);
    cudaGetSymbolAddress((void**)&p_scores, g_scores);
    cudaGetSymbolAddress((void**)&p_ctx, g_ctx);
    cudaGetSymbolAddress((void**)&p_t2, g_t2);
    cudaGetSymbolAddress((void**)&p_qn, g_qn);
    cudaGetSymbolAddress((void**)&p_sn, g_sn);
    cudaGetSymbolAddress((void**)&p_cq, g_cq);
    cudaGetSymbolAddress((void**)&p_ckv, g_ckv);
    cudaGetSymbolAddress((void**)&p_upd, g_upd);
    cudaGetSymbolAddress((void**)&p_gacc, g_gacc);
    cudaGetSymbolAddress((void**)&p_t3, g_t3);
    cudaGetSymbolAddress((void**)&p_gu, g_gu);
    cudaGetSymbolAddress((void**)&p_act, g_act);
    cudaGetSymbolAddress((void**)&p_ss, g_ss);
    cudaGetSymbolAddress((void**)&p_vrow, g_vrow);
    cudaGetSymbolAddress((void**)&p_valid, g_valid);
    cudaGetSymbolAddress((void**)&p_svalid, g_svalid);

    const int BH = Bc*Hc;                     // 64
    const long long SS = (long long)Sc*Sc;    // 1M

    // 1) mask layout detect + decode
    detect_mask_layout<<<(Bc*Sc+255)/256,256>>>((const unsigned char*)padding_mask, Bc*Sc, 0);
    detect_mask_layout<<<(Bc*Lc+255)/256,256>>>((const unsigned char*)seq_mask,     Bc*Lc, 1);
    decode_mask<<<Bc,256>>>(padding_mask, Sc, 0, p_valid,  nullptr);
    decode_mask<<<Bc,256>>>(seq_mask,     Lc, 1, p_svalid, p_vrow);

    // 2) FiLM params: [B, 2D]
    film_gemv<<<(Bc*2*Dc*32 + 255)/256, 256>>>(modulation, film_w, film_b, p_ss, Bc, 2*Dc, Dc);

    // 3) x = FiLM(rmsnorm(tokens))
    rmsnorm_kernel<<<BSc,256>>>(tokens, attn_norm_w, p_x, Dc, p_ss, Sc);

    // 4) qkv = x @ qkv_w^T + qkv_b
    tc_nt(p_x, qkv_w, p_qkv, BSc, 3*Dc, Dc, Dc, Dc, 3*Dc,
          1.f, qkv_b, nullptr, 0, nullptr, 1, 0);

    // 5) RoPE on q,k
    rope_kernel<<<((long)BSc*Hc*(HDc/2) + 255)/256, 256>>>(p_qkv);

    // 6) self-attn scores = (q @ k^T)/8, batched over (b,h)
    tc_nt(p_qkv, p_qkv + Dc, p_scores, Sc, Sc, HDc, 3*Dc, 3*Dc, Sc,
          0.125f, nullptr, nullptr, 0, nullptr, 1, 0,
          BH, Hc,
          (long long)Sc*3*Dc, HDc, (long long)Sc*3*Dc, HDc,
          (long long)Hc*SS, SS);

    // 7) masked softmax
    { dim3 g(1, Sc, BH); softmax_mask_kernel<<<g,256>>>(p_scores, p_valid, Sc, Hc); }

    // 8) ctx = P @ V
    tc_nn_pv(p_scores, p_qkv + 2*Dc, p_ctx, Sc, HDc, Sc, Sc, 3*Dc, Dc,
             BH, Hc,
             (long long)Hc*SS, SS, (long long)Sc*3*Dc, HDc,
             (long long)Sc*Dc, HDc);

    // 9) tokens2 = tokens + ctx @ out_w^T + out_b
    tc_nt(p_ctx, out_w, p_t2, BSc, Dc, Dc, Dc, Dc, Dc,
          1.f, out_b, tokens, Dc, nullptr, 1, 0);

    // 10) query / src norms
    rmsnorm_kernel<<<BSc,256>>>(p_t2, sq_norm_w, p_qn, Dc, nullptr, Sc);
    rmsnorm_kernel<<<BLc,256>>>(seq_tokens, s_norm_w, p_sn, Dc, nullptr, Lc);

    // 11) cq = qn @ wq^T + bq ; ckv = sn @ [wk;wv]^T + [bk;bv]
    tc_nt(p_qn, mha_in_w, p_cq, BSc, Dc, Dc, Dc, Dc, Dc,
          1.f, mha_in_b, nullptr, 0, nullptr, 1, 0);
    tc_nt(p_sn, mha_in_w + (long long)Dc*Dc, p_ckv, BLc, 2*Dc, Dc, Dc, Dc, 2*Dc,
          1.f, mha_in_b + Dc, nullptr, 0, nullptr, 1, 0);

    // 12) cross scores = (cq @ ck^T)/8
    tc_nt(p_cq, p_ckv, p_scores, Sc, Lc, HDc, Dc, 2*Dc, Lc,
          0.125f, nullptr, nullptr, 0, nullptr, 1, 0,
          BH, Hc,
          (long long)Sc*Dc, HDc, (long long)Lc*2*Dc, HDc,
          (long long)Hc*SS, SS);

    // 13) masked softmax (seq mask)
    { dim3 g(1, Sc, BH); softmax_mask_kernel<<<g,256>>>(p_scores, p_svalid, Lc, Hc); }

    // 14) ctx2 = P @ cv
    tc_nn_pv(p_scores, p_ckv + Dc, p_ctx, Sc, HDc, Lc, Lc, 2*Dc, Dc,
             BH, Hc,
             (long long)Hc*SS, SS, (long long)Lc*2*Dc, HDc,
             (long long)Sc*Dc, HDc);

    // 15) update = (ctx2 @ mha_out_w^T + mha_out_b) * valid_rows[b]
    tc_nt(p_ctx, mha_out_w, p_upd, BSc, Dc, Dc, Dc, Dc, Dc,
          1.f, mha_out_b, nullptr, 0, p_vrow, Sc, 0);

    // 16) gate pre-activation: gacc = t2 @ gate_w[:, :D]^T + upd @ gate_w[:, D:]^T
    tc_nt(p_t2,  gate_w,      p_gacc, BSc, Dc, Dc, Dc, 2*Dc, Dc,
          1.f, nullptr, nullptr, 0, nullptr, 1, 0);
    tc_nt(p_upd, gate_w + Dc, p_gacc, BSc, Dc, Dc, Dc, 2*Dc, Dc,
          1.f, nullptr, nullptr, 0, nullptr, 1, 1);

    // 17) t3 = t2 + sigmoid(gacc + gate_b) * upd
    gate_fuse_kernel<<<((long)BSc*Dc + 255)/256, 256>>>(p_t2, p_gacc, gate_b, p_upd, p_t3,
                                                        (long)BSc*Dc, Dc);

    // 18) h = rmsnorm(t3, ffn_norm_w) (reuse g_x)
    rmsnorm_kernel<<<BSc,256>>>(p_t3, ffn_norm_w, p_x, Dc, nullptr, Sc);

    // 19) gu = h @ gu_w^T + gu_b
    tc_nt(p_x, gu_w, p_gu, BSc, 2*HIDc, Dc, Dc, Dc, 2*HIDc,
          1.f, gu_b, nullptr, 0, nullptr, 1, 0);

    // 20) act = silu(g) * val
    silu_kernel<<<((long)BSc*HIDc + 255)/256, 256>>>(p_gu, p_act, BSc);

    // 21) out = t3 + act @ down_w^T + down_b
    tc_nt(p_act, down_w, out, BSc, Dc, HIDc, HIDc, HIDc, Dc,
          1.f, down_b, p_t3, Dc, nullptr, 1, 0);
}

// round 3
// speedup vs baseline: 3.0446x; 1.4599x over previous
#include <cuda_runtime.h>
#include <cuda_bf16.h>
#include <cuda_fp16.h>
#include <math.h>

// Problem constants (PCVRSymbiosis): B=4, S=1024, L=1024, D=1024, H=16, HD=64, HIDDEN=4096
#define Bc 4
#define Sc 1024
#define Lc 1024
#define Dc 1024
#define Hc 16
#define HDc 64
#define HIDc 4096
#define BSc (Bc*Sc)
#define BLc (Bc*Lc)

// ---------------- scratch (static device globals; no runtime alloc) ----------------
__device__ float g_x    [BSc*Dc];
__device__ float g_qkv  [BSc*3*Dc];
__device__ float g_scores[(size_t)Bc*Hc*Sc*Sc];
__device__ float g_ctx  [BSc*Dc];
__device__ float g_t2   [BSc*Dc];
__device__ float g_qn   [BSc*Dc];
__device__ float g_sn   [BLc*Dc];
__device__ float g_cq   [BSc*Dc];
__device__ float g_ckv  [BLc*2*Dc];
__device__ float g_upd  [BSc*Dc];
__device__ float g_gacc [BSc*Dc];
__device__ float g_t3   [BSc*Dc];
__device__ float g_gu   [(size_t)BSc*2*HIDc];
__device__ float g_act  [(size_t)BSc*HIDc];
__device__ float g_ss   [Bc*2*Dc];
__device__ int   g_valid [BSc];
__device__ int   g_svalid[BLc];
__device__ float g_vrow  [Bc];
__device__ int   g_layout[2];

// ---------------- reductions ----------------
__device__ __forceinline__ float warp_sum(float v){
    #pragma unroll
    for (int o=16;o>0;o>>=1) v += __shfl_xor_sync(0xffffffffu, v, o);
    return v;
}
__device__ __forceinline__ float warp_max(float v){
    #pragma unroll
    for (int o=16;o>0;o>>=1) v = fmaxf(v, __shfl_xor_sync(0xffffffffu, v, o));
    return v;
}
__device__ float block_sum(float v){
    __shared__ float red[33];
    __syncthreads();
    int lane = threadIdx.x & 31, wid = threadIdx.x >> 5;
    v = warp_sum(v);
    if (lane==0) red[wid] = v;
    __syncthreads();
    int nw = blockDim.x >> 5;
    float r = (threadIdx.x < nw) ? red[threadIdx.x] : 0.f;
    if (wid==0){ r = warp_sum(r); if (lane==0) red[32] = r; }
    __syncthreads();
    return red[32];
}
__device__ float block_max(float v){
    __shared__ float red[33];
    __syncthreads();
    int lane = threadIdx.x & 31, wid = threadIdx.x >> 5;
    v = warp_max(v);
    if (lane==0) red[wid] = v;
    __syncthreads();
    int nw = blockDim.x >> 5;
    float r = (threadIdx.x < nw) ? red[threadIdx.x] : -3.4e38f;
    if (wid==0){ r = warp_max(r); if (lane==0) red[32] = r; }
    __syncthreads();
    return red[32];
}

// ---------------- mask layout detection + decode ----------------
__global__ void detect_mask_layout(const unsigned char* __restrict__ p, int n, int slot){
    int i = blockIdx.x*blockDim.x + threadIdx.x;
    if (i >= n) return;
    unsigned char v = p[i];
    if (v != 0 && v != 1) atomicOr(&g_layout[slot], 2);
    else if (v == 1 && (i & 3) != 0) atomicOr(&g_layout[slot], 1);
}
__global__ void decode_mask(const void* __restrict__ p, int cols, int slot,
                            int* __restrict__ valid, float* __restrict__ vrow){
    int b = blockIdx.x;
    int layout = g_layout[slot];
    int mode = (layout & 2) ? 2 : ((layout & 1) ? 1 : 0);
    __shared__ int s_anyzero;
    if (threadIdx.x==0) s_anyzero = 0;
    __syncthreads();
    int local_any = 0;
    for (int j = threadIdx.x; j < cols; j += blockDim.x){
        long idx = (long)b*cols + j;
        int m;
        if (mode==1)      m = ((const unsigned char*)p)[idx] != 0;
        else if (mode==2) m = ((const float*)p)[idx] != 0.f;
        else              m = ((const int*)p)[idx] != 0;
        valid[idx] = m;
        if (!m) local_any = 1;
    }
    if (local_any) atomicOr(&s_anyzero, 1);
    __syncthreads();
    int anyz = s_anyzero;
    for (int j = threadIdx.x; j < cols; j += blockDim.x){
        long idx = (long)b*cols + j;
        valid[idx] = anyz ? (1 - valid[idx]) : 1;
    }
    if (vrow && threadIdx.x==0) vrow[b] = anyz ? 1.f : 0.f;
}

// ---------------- mma helpers ----------------
__device__ __forceinline__ unsigned f2tf(float x){
    unsigned u; asm("cvt.rna.tf32.f32 %0, %1;" : "=r"(u) : "f"(x)); return u;
}
__device__ __forceinline__ void mma_tf32(float* c, const unsigned* a, const unsigned* b){
    asm volatile("mma.sync.aligned.m16n8k8.row.col.f32.tf32.tf32.f32 "
        "{%0,%1,%2,%3}, {%4,%5,%6,%7}, {%8,%9}, {%0,%1,%2,%3};"
        : "+f"(c[0]),"+f"(c[1]),"+f"(c[2]),"+f"(c[3])
        : "r"(a[0]),"r"(a[1]),"r"(a[2]),"r"(a[3]), "r"(b[0]),"r"(b[1]));
}
__device__ __forceinline__ void mma_f16(float* c, const unsigned* a, const unsigned* b){
    asm volatile("mma.sync.aligned.m16n8k16.row.col.f32.f16.f16.f32 "
        "{%0,%1,%2,%3}, {%4,%5,%6,%7}, {%8,%9}, {%0,%1,%2,%3};"
        : "+f"(c[0]),"+f"(c[1]),"+f"(c[2]),"+f"(c[3])
        : "r"(a[0]),"r"(a[1]),"r"(a[2]),"r"(a[3]), "r"(b[0]),"r"(b[1]));
}
__device__ __forceinline__ unsigned pack_h2(float x, float y){
    __half2 h = __floats2half2_rn(x, y);
    return *(unsigned*)&h;
}

// ---------------- fp16 tensor-core NT GEMM: C = alpha * A @ B^T + epilogue ----------------
// A [M,K] row-major, B [N,K] row-major. M%128==0, N%128==0, K%16==0 required.
template<int NWM,int NWN>
__global__ __launch_bounds__(NWM*NWN*32)
void gemm_h16(const float* __restrict__ A, const float* __restrict__ B,
              float* __restrict__ C,
              int M,int N,int K,int lda,int ldb,int ldc,
              int batH,
              long long aO,long long aI,long long bO,long long bI,
              long long cO,long long cI,
              float alpha,
              const float* __restrict__ bias,
              const float* __restrict__ residual,int ldres,
              const float* __restrict__ rowscale,int rsDiv,
              int accum)
{
    constexpr int BM = 128, BN = 128, BK = 16;
    constexpr int NT = NWM*NWN*32;         // 256
    constexpr int WM = BM/NWM, WN = BN/NWN;
    constexpr int MI = WM/16, NI = WN/8;
    constexpr int LDS_H = BK + 8;          // 24 halves per row -> conflict-free frag loads

    __shared__ __align__(16) __half As[BM*LDS_H];
    __shared__ __align__(16) __half Bs[BN*LDS_H];

    const int tid = threadIdx.x, lane = tid & 31, warp = tid >> 5;
    const int z = blockIdx.z;
    const float* Ab = A + (long long)(z/batH)*aO + (long long)(z%batH)*aI;
    const float* Bb = B + (long long)(z/batH)*bO + (long long)(z%batH)*bI;
    float*       Cb = C + (long long)(z/batH)*cO + (long long)(z%batH)*cI;

    const int m0 = blockIdx.y*BM, n0 = blockIdx.x*BN;
    const int wm0 = (warp/NWN)*WM, wn0 = (warp%NWN)*WN;
    const int qr = lane >> 2, qc = lane & 3;

    float acc[MI][NI][4];
    #pragma unroll
    for (int i=0;i<MI;i++)
        #pragma unroll
        for (int j=0;j<NI;j++)
            #pragma unroll
            for (int r=0;r<4;r++) acc[i][j][r]=0.f;

    constexpr int AF4 = (BM*BK)/(4*NT);    // 2
    constexpr int BF4 = (BN*BK)/(4*NT);    // 2
    float4 ra[AF4], rb[BF4];

    const int nk = K/BK;
    const int sm = tid>>2, skq = tid&3;    // staging coords: row = tid/4, k-quad = tid%4

    // prologue loads
    #pragma unroll
    for (int it=0; it<AF4; ++it)
        ra[it] = *(const float4*)(Ab + (long long)(m0+sm+it*(NT/4))*lda + skq*4);
    #pragma unroll
    for (int it=0; it<BF4; ++it)
        rb[it] = *(const float4*)(Bb + (long long)(n0+sm+it*(NT/4))*ldb + skq*4);

    for (int kt=0; kt<nk; ++kt){
        __syncthreads();
        #pragma unroll
        for (int it=0; it<AF4; ++it){
            int m = sm + it*(NT/4);
            *(uint2*)&As[m*LDS_H + skq*4] =
                make_uint2(pack_h2(ra[it].x, ra[it].y), pack_h2(ra[it].z, ra[it].w));
        }
        #pragma unroll
        for (int it=0; it<BF4; ++it){
            int n = sm + it*(NT/4);
            *(uint2*)&Bs[n*LDS_H + skq*4] =
                make_uint2(pack_h2(rb[it].x, rb[it].y), pack_h2(rb[it].z, rb[it].w));
        }
        __syncthreads();
        if (kt+1 < nk){
            int k0 = (kt+1)*BK;
            #pragma unroll
            for (int it=0; it<AF4; ++it)
                ra[it] = *(const float4*)(Ab + (long long)(m0+sm+it*(NT/4))*lda + k0 + skq*4);
            #pragma unroll
            for (int it=0; it<BF4; ++it)
                rb[it] = *(const float4*)(Bb + (long long)(n0+sm+it*(NT/4))*ldb + k0 + skq*4);
        }
        // one m16n8k16 step covers the whole BK=16 tile
        unsigned af[MI][4], bf[NI][2];
        #pragma unroll
        for (int mi=0; mi<MI; ++mi){
            int mr = wm0 + mi*16 + qr;
            af[mi][0] = *(const unsigned*)&As[ mr   *LDS_H + 2*qc    ];
            af[mi][1] = *(const unsigned*)&As[(mr+8)*LDS_H + 2*qc    ];
            af[mi][2] = *(const unsigned*)&As[ mr   *LDS_H + 2*qc + 8];
            af[mi][3] = *(const unsigned*)&As[(mr+8)*LDS_H + 2*qc + 8];
        }
        #pragma unroll
        for (int ni=0; ni<NI; ++ni){
            int nc = wn0 + ni*8 + qr;
            bf[ni][0] = *(const unsigned*)&Bs[nc*LDS_H + 2*qc    ];
            bf[ni][1] = *(const unsigned*)&Bs[nc*LDS_H + 2*qc + 8];
        }
        #pragma unroll
        for (int mi=0; mi<MI; ++mi)
            #pragma unroll
            for (int ni=0; ni<NI; ++ni)
                mma_f16(acc[mi][ni], af[mi], bf[ni]);
    }

    // epilogue
    #pragma unroll
    for (int mi=0; mi<MI; ++mi){
        #pragma unroll
        for (int half=0; half<2; ++half){
            int gm = m0 + wm0 + mi*16 + qr + half*8;
            float rs = rowscale ? rowscale[gm/rsDiv] : 1.f;
            #pragma unroll
            for (int ni=0; ni<NI; ++ni){
                int gn = n0 + wn0 + ni*8 + qc*2;
                float v0 = alpha*acc[mi][ni][half*2+0];
                float v1 = alpha*acc[mi][ni][half*2+1];
                if (bias){ v0 += bias[gn]; v1 += bias[gn+1]; }
                v0 *= rs; v1 *= rs;
                if (residual){
                    float2 r = *(const float2*)(residual + (long long)gm*ldres + gn);
                    v0 += r.x; v1 += r.y;
                }
                long long off = (long long)gm*ldc + gn;
                if (accum){ float2 c0 = *(float2*)(Cb+off); v0 += c0.x; v1 += c0.y; }
                *(float2*)(Cb+off) = make_float2(v0, v1);
            }
        }
    }
}

// ---------------- tf32 NN GEMM (PV only): C = A @ B ----------------
template<int BM,int BN,int NWM,int NWN>
__global__ __launch_bounds__(NWM*NWN*32)
void gemm_tc_nn(const float* __restrict__ A, const float* __restrict__ B,
                float* __restrict__ C,
                int M,int N,int K,int lda,int ldb,int ldc,
                int batH,
                long long aO,long long aI,long long bO,long long bI,
                long long cO,long long cI)
{
    constexpr int BK = 16;
    constexpr int NT = NWM*NWN*32;
    constexpr int WM = BM/NWM, WN = BN/NWN;
    constexpr int MI = WM/16, NI = WN/8;
    constexpr int LDA_S = BK+4;
    constexpr int LDB_S = BN+8;

    __shared__ unsigned As[BM*LDA_S];
    __shared__ unsigned Bs[BK*LDB_S];

    const int tid = threadIdx.x, lane = tid & 31, warp = tid >> 5;
    const int z = blockIdx.z;
    const float* Ab = A + (long long)(z/batH)*aO + (long long)(z%batH)*aI;
    const float* Bb = B + (long long)(z/batH)*bO + (long long)(z%batH)*bI;
    float*       Cb = C + (long long)(z/batH)*cO + (long long)(z%batH)*cI;

    const int m0 = blockIdx.y*BM, n0 = blockIdx.x*BN;
    const int wm0 = (warp/NWN)*WM, wn0 = (warp%NWN)*WN;
    const int qr = lane >> 2, qc = lane & 3;

    float acc[MI][NI][4];
    #pragma unroll
    for (int i=0;i<MI;i++)
        #pragma unroll
        for (int j=0;j<NI;j++)
            #pragma unroll
            for (int r=0;r<4;r++) acc[i][j][r]=0.f;

    constexpr int AF4 = (BM*BK)/(4*NT);
    constexpr int BF4 = (BN*BK)/(4*NT);
    float4 ra[AF4], rb[BF4];

    const int nk = K/BK;

    #pragma unroll
    for (int it=0; it<AF4; ++it){
        int idx = tid + it*NT; int m = idx>>2, kq = idx&3;
        ra[it] = *(const float4*)(Ab + (long long)(m0+m)*lda + kq*4);
    }
    #pragma unroll
    for (int it=0; it<BF4; ++it){
        int idx = tid + it*NT; int kl = idx/(BN/4), nq = idx%(BN/4);
        rb[it] = *(const float4*)(Bb + (long long)kl*ldb + n0 + nq*4);
    }

    for (int kt=0; kt<nk; ++kt){
        __syncthreads();
        #pragma unroll
        for (int it=0; it<AF4; ++it){
            int idx = tid + it*NT; int m = idx>>2, kq = idx&3;
            unsigned* d = &As[m*LDA_S + kq*4];
            d[0]=f2tf(ra[it].x); d[1]=f2tf(ra[it].y); d[2]=f2tf(ra[it].z); d[3]=f2tf(ra[it].w);
        }
        #pragma unroll
        for (int it=0; it<BF4; ++it){
            int idx = tid + it*NT; int kl = idx/(BN/4), nq = idx%(BN/4);
            unsigned* d = &Bs[kl*LDB_S + nq*4];
            d[0]=f2tf(rb[it].x); d[1]=f2tf(rb[it].y); d[2]=f2tf(rb[it].z); d[3]=f2tf(rb[it].w);
        }
        __syncthreads();
        if (kt+1 < nk){
            int k0 = (kt+1)*BK;
            #pragma unroll
            for (int it=0; it<AF4; ++it){
                int idx = tid + it*NT; int m = idx>>2, kq = idx&3;
                ra[it] = *(const float4*)(Ab + (long long)(m0+m)*lda + k0 + kq*4);
            }
            #pragma unroll
            for (int it=0; it<BF4; ++it){
                int idx = tid + it*NT; int kl = idx/(BN/4), nq = idx%(BN/4);
                rb[it] = *(const float4*)(Bb + (long long)(k0+kl)*ldb + n0 + nq*4);
            }
        }
        #pragma unroll
        for (int ks=0; ks<BK; ks+=8){
            unsigned af[MI][4], bf[NI][2];
            #pragma unroll
            for (int mi=0; mi<MI; ++mi){
                int mr = wm0 + mi*16 + qr;
                af[mi][0] = As[ mr   *LDA_S + ks+qc  ];
                af[mi][1] = As[(mr+8)*LDA_S + ks+qc  ];
                af[mi][2] = As[ mr   *LDA_S + ks+qc+4];
                af[mi][3] = As[(mr+8)*LDA_S + ks+qc+4];
            }
            #pragma unroll
            for (int ni=0; ni<NI; ++ni){
                int nc = wn0 + ni*8 + qr;
                bf[ni][0] = Bs[(ks+qc  )*LDB_S + nc];
                bf[ni][1] = Bs[(ks+qc+4)*LDB_S + nc];
            }
            #pragma unroll
            for (int mi=0; mi<MI; ++mi)
                #pragma unroll
                for (int ni=0; ni<NI; ++ni)
                    mma_tf32(acc[mi][ni], af[mi], bf[ni]);
        }
    }

    #pragma unroll
    for (int mi=0; mi<MI; ++mi){
        #pragma unroll
        for (int half=0; half<2; ++half){
            int gm = m0 + wm0 + mi*16 + qr + half*8;
            #pragma unroll
            for (int ni=0; ni<NI; ++ni){
                int gn = n0 + wn0 + ni*8 + qc*2;
                long long off = (long long)gm*ldc + gn;
                *(float2*)(Cb+off) = make_float2(acc[mi][ni][half*2+0], acc[mi][ni][half*2+1]);
            }
        }
    }
}

// ---------------- small fused kernels ----------------
__global__ void film_gemv(const float* __restrict__ mod, const float* __restrict__ W,
                          const float* __restrict__ bias, float* __restrict__ out,
                          int Bn, int N2, int K){
    int warp = (blockIdx.x*blockDim.x + threadIdx.x) >> 5;
    int lane = threadIdx.x & 31;
    if (warp >= Bn*N2) return;
    int b = warp / N2, n = warp % N2;
    const float* a = mod + (long)b*K;
    const float* w = W   + (long)n*K;
    float acc=0.f;
    for (int k=lane; k<K; k+=32) acc = fmaf(a[k], w[k], acc);
    acc = warp_sum(acc);
    if (lane==0) out[warp] = acc + bias[n];
}

__global__ void rmsnorm_kernel(const float* __restrict__ x, const float* __restrict__ w,
                               float* __restrict__ y, int Dd,
                               const float* __restrict__ filmss, int S){
    long row = blockIdx.x;
    const float* xr = x + row*Dd;
    float ss = 0.f;
    for (int j = threadIdx.x; j < Dd; j += blockDim.x){ float v = xr[j]; ss = fmaf(v,v,ss); }
    ss = block_sum(ss);
    float r = rsqrtf(ss/(float)Dd + 1e-6f);
    if (filmss){
        int b = (int)(row / S);
        const float* sc = filmss + (long)b*2*Dd;
        for (int j = threadIdx.x; j < Dd; j += blockDim.x){
            float v = xr[j]*r*w[j];
            y[row*Dd + j] = v*(1.f + 0.1f*tanhf(sc[j])) + sc[Dd + j];
        }
    } else {
        for (int j = threadIdx.x; j < Dd; j += blockDim.x)
            y[row*Dd + j] = xr[j]*r*w[j];
    }
}

__global__ void rope_kernel(float* __restrict__ qkv){
    long idx = (long)blockIdx.x*blockDim.x + threadIdx.x;
    const long total = (long)BSc * Hc * (HDc/2);
    if (idx >= total) return;
    int i = idx % (HDc/2);
    int h = (idx / (HDc/2)) % Hc;
    long row = idx / ((HDc/2)*Hc);
    int s = (int)(row % Sc);
    float freq = expf(-logf(10000.f) * (float)(2*i) / (float)HDc);
    float ang = (float)s * freq;
    float c = cosf(ang), sn = sinf(ang);
    float* qb = qkv + row*(3*Dc) + h*HDc;
    float e = qb[2*i], o = qb[2*i+1];
    qb[2*i]   = e*c - o*sn;
    qb[2*i+1] = e*sn + o*c;
    float* kb = qb + Dc;
    e = kb[2*i]; o = kb[2*i+1];
    kb[2*i]   = e*c - o*sn;
    kb[2*i+1] = e*sn + o*c;
}

__global__ void softmax_mask_kernel(float* __restrict__ scores, const int* __restrict__ valid,
                                    int cols, int Hh){
    __shared__ float buf[1024];
    int z = blockIdx.z;
    int b = z / Hh;
    float* row = scores + ((long long)z*gridDim.y + blockIdx.y)*cols;
    const int* vl = valid + (long)b*cols;
    float mx = -3.4e38f;
    for (int j=threadIdx.x; j<cols; j+=blockDim.x){
        float v = vl[j] ? row[j] : -3.4e38f;
        buf[j] = v;
        mx = fmaxf(mx, v);
    }
    mx = block_max(mx);
    float sm = 0.f;
    for (int j=threadIdx.x; j<cols; j+=blockDim.x){
        float e = expf(buf[j]-mx);
        buf[j] = e; sm += e;
    }
    sm = block_sum(sm);
    float inv = 1.f/sm;
    for (int j=threadIdx.x; j<cols; j+=blockDim.x) row[j] = buf[j]*inv;
}

__global__ void gate_fuse_kernel(const float* __restrict__ t2, const float* __restrict__ gacc,
                                 const float* __restrict__ gate_b, const float* __restrict__ upd,
                                 float* __restrict__ t3, long n, int Dd){
    long i = (long)blockIdx.x*blockDim.x + threadIdx.x;
    if (i >= n) return;
    float g = gacc[i] + gate_b[i % Dd];
    float sg = 1.f / (1.f + expf(-g));
    t3[i] = t2[i] + sg * upd[i];
}

__global__ void silu_kernel(const float* __restrict__ gu, float* __restrict__ act, long rows){
    long i = (long)blockIdx.x*blockDim.x + threadIdx.x;
    long n = rows * HIDc;
    if (i >= n) return;
    long m = i / HIDc; int j = (int)(i % HIDc);
    float g = gu[m*(2*HIDc) + j];
    float v = gu[m*(2*HIDc) + HIDc + j];
    float s = g / (1.f + expf(-g));
    act[i] = s * v;
}

// ---------------- host-side launch helpers ----------------
static inline void tc_nt(const float* A,const float* B,float* C,
    int M,int N,int K,int lda,int ldb,int ldc,
    float alpha,const float* bias,const float* res,int ldres,
    const float* rs,int rsdiv,int accum,
    int zc=1,int batH=1,
    long long aO=0,long long aI=0,long long bO=0,long long bI=0,
    long long cO=0,long long cI=0)
{
    dim3 g(N/128, M/128, zc);
    gemm_h16<2,4><<<g,256>>>(A,B,C,M,N,K,lda,ldb,ldc,batH,
        aO,aI,bO,bI,cO,cI,alpha,bias,res,ldres,rs,rsdiv,accum);
}
static inline void tc_nn_pv(const float* A,const float* B,float* C,
    int M,int N,int K,int lda,int ldb,int ldc,
    int zc,int batH,
    long long aO,long long aI,long long bO,long long bI,
    long long cO,long long cI)
{
    dim3 g(N/64, M/128, zc);
    gemm_tc_nn<128,64,4,2><<<g,256>>>(A,B,C,M,N,K,lda,ldb,ldc,batH,
        aO,aI,bO,bI,cO,cI);
}

extern "C" void kernel_launch(void* const* d_in, const int* in_sizes, int n_in,
                              void* d_out, int out_size)
{
    const float* tokens     = (const float*)d_in[0];
    const float* seq_tokens = (const float*)d_in[1];
    const float* modulation = (const float*)d_in[2];
    const float* attn_norm_w= (const float*)d_in[3];
    const float* qkv_w      = (const float*)d_in[4];
    const float* qkv_b      = (const float*)d_in[5];
    const float* out_w      = (const float*)d_in[6];
    const float* out_b      = (const float*)d_in[7];
    const float* film_w     = (const float*)d_in[8];
    const float* film_b     = (const float*)d_in[9];
    const float* sq_norm_w  = (const float*)d_in[10];
    const float* s_norm_w   = (const float*)d_in[11];
    const float* mha_in_w   = (const float*)d_in[12];
    const float* mha_in_b   = (const float*)d_in[13];
    const float* mha_out_w  = (const float*)d_in[14];
    const float* mha_out_b  = (const float*)d_in[15];
    const float* gate_w     = (const float*)d_in[16];
    const float* gate_b     = (const float*)d_in[17];
    const float* ffn_norm_w = (const float*)d_in[18];
    const float* gu_w       = (const float*)d_in[19];
    const float* gu_b       = (const float*)d_in[20];
    const float* down_w     = (const float*)d_in[21];
    const float* down_b     = (const float*)d_in[22];
    const void*  padding_mask = d_in[23];
    const void*  seq_mask     = d_in[24];
    float* out = (float*)d_out;

    float *p_x,*p_qkv,*p_scores,*p_ctx,*p_t2,*p_qn,*p_sn,*p_cq,*p_ckv,*p_upd,*p_gacc,*p_t3,*p_gu,*p_act,*p_ss,*p_vrow;
    int *p_valid,*p_svalid;
    cudaGetSymbolAddress((void**)&p_x, g_x);
    cudaGetSymbolAddress((void**)&p_qkv, g_qkv);
    cudaGetSymbolAddress((void**)&p_scores, g_scores);
    cudaGetSymbolAddress((void**)&p_ctx, g_ctx);
    cudaGetSymbolAddress((void**)&p_t2, g_t2);
    cudaGetSymbolAddress((void**)&p_qn, g_qn);
    cudaGetSymbolAddress((void**)&p_sn, g_sn);
    cudaGetSymbolAddress((void**)&p_cq, g_cq);
    cudaGetSymbolAddress((void**)&p_ckv, g_ckv);
    cudaGetSymbolAddress((void**)&p_upd, g_upd);
    cudaGetSymbolAddress((void**)&p_gacc, g_gacc);
    cudaGetSymbolAddress((void**)&p_t3, g_t3);
    cudaGetSymbolAddress((void**)&p_gu, g_gu);
    cudaGetSymbolAddress((void**)&p_act, g_act);
    cudaGetSymbolAddress((void**)&p_ss, g_ss);
    cudaGetSymbolAddress((void**)&p_vrow, g_vrow);
    cudaGetSymbolAddress((void**)&p_valid, g_valid);
    cudaGetSymbolAddress((void**)&p_svalid, g_svalid);

    const int BH = Bc*Hc;                     // 64
    const long long SS = (long long)Sc*Sc;    // 1M

    // 1) mask layout detect + decode
    detect_mask_layout<<<(Bc*Sc+255)/256,256>>>((const unsigned char*)padding_mask, Bc*Sc, 0);
    detect_mask_layout<<<(Bc*Lc+255)/256,256>>>((const unsigned char*)seq_mask,     Bc*Lc, 1);
    decode_mask<<<Bc,256>>>(padding_mask, Sc, 0, p_valid,  nullptr);
    decode_mask<<<Bc,256>>>(seq_mask,     Lc, 1, p_svalid, p_vrow);

    // 2) FiLM params: [B, 2D]
    film_gemv<<<(Bc*2*Dc*32 + 255)/256, 256>>>(modulation, film_w, film_b, p_ss, Bc, 2*Dc, Dc);

    // 3) x = FiLM(rmsnorm(tokens))
    rmsnorm_kernel<<<BSc,256>>>(tokens, attn_norm_w, p_x, Dc, p_ss, Sc);

    // 4) qkv = x @ qkv_w^T + qkv_b
    tc_nt(p_x, qkv_w, p_qkv, BSc, 3*Dc, Dc, Dc, Dc, 3*Dc,
          1.f, qkv_b, nullptr, 0, nullptr, 1, 0);

    // 5) RoPE on q,k
    rope_kernel<<<((long)BSc*Hc*(HDc/2) + 255)/256, 256>>>(p_qkv);

    // 6) self-attn scores = (q @ k^T)/8, batched over (b,h)
    tc_nt(p_qkv, p_qkv + Dc, p_scores, Sc, Sc, HDc, 3*Dc, 3*Dc, Sc,
          0.125f, nullptr, nullptr, 0, nullptr, 1, 0,
          BH, Hc,
          (long long)Sc*3*Dc, HDc, (long long)Sc*3*Dc, HDc,
          (long long)Hc*SS, SS);

    // 7) masked softmax
    { dim3 g(1, Sc, BH); softmax_mask_kernel<<<g,256>>>(p_scores, p_valid, Sc, Hc); }

    // 8) ctx = P @ V
    tc_nn_pv(p_scores, p_qkv + 2*Dc, p_ctx, Sc, HDc, Sc, Sc, 3*Dc, Dc,
             BH, Hc,
             (long long)Hc*SS, SS, (long long)Sc*3*Dc, HDc,
             (long long)Sc*Dc, HDc);

    // 9) tokens2 = tokens + ctx @ out_w^T + out_b
    tc_nt(p_ctx, out_w, p_t2, BSc, Dc, Dc, Dc, Dc, Dc,
          1.f, out_b, tokens, Dc, nullptr, 1, 0);

    // 10) query / src norms
    rmsnorm_kernel<<<BSc,256>>>(p_t2, sq_norm_w, p_qn, Dc, nullptr, Sc);
    rmsnorm_kernel<<<BLc,256>>>(seq_tokens, s_norm_w, p_sn, Dc, nullptr, Lc);

    // 11) cq = qn @ wq^T + bq ; ckv = sn @ [wk;wv]^T + [bk;bv]
    tc_nt(p_qn, mha_in_w, p_cq, BSc, Dc, Dc, Dc, Dc, Dc,
          1.f, mha_in_b, nullptr, 0, nullptr, 1, 0);
    tc_nt(p_sn, mha_in_w + (long long)Dc*Dc, p_ckv, BLc, 2*Dc, Dc, Dc, Dc, 2*Dc,
          1.f, mha_in_b + Dc, nullptr, 0, nullptr, 1, 0);

    // 12) cross scores = (cq @ ck^T)/8
    tc_nt(p_cq, p_ckv, p_scores, Sc, Lc, HDc, Dc, 2*Dc, Lc,
          0.125f, nullptr, nullptr, 0, nullptr, 1, 0,
          BH, Hc,
          (long long)Sc*Dc, HDc, (long long)Lc*2*Dc, HDc,
          (long long)Hc*SS, SS);

    // 13) masked softmax (seq mask)
    { dim3 g(1, Sc, BH); softmax_mask_kernel<<<g,256>>>(p_scores, p_svalid, Lc, Hc); }

    // 14) ctx2 = P @ cv
    tc_nn_pv(p_scores, p_ckv + Dc, p_ctx, Sc, HDc, Lc, Lc, 2*Dc, Dc,
             BH, Hc,
             (long long)Hc*SS, SS, (long long)Lc*2*Dc, HDc,
             (long long)Sc*Dc, HDc);

    // 15) update = (ctx2 @ mha_out_w^T + mha_out_b) * valid_rows[b]
    tc_nt(p_ctx, mha_out_w, p_upd, BSc, Dc, Dc, Dc, Dc, Dc,
          1.f, mha_out_b, nullptr, 0, p_vrow, Sc, 0);

    // 16) gate pre-activation: gacc = t2 @ gate_w[:, :D]^T + upd @ gate_w[:, D:]^T
    tc_nt(p_t2,  gate_w,      p_gacc, BSc, Dc, Dc, Dc, 2*Dc, Dc,
          1.f, nullptr, nullptr, 0, nullptr, 1, 0);
    tc_nt(p_upd, gate_w + Dc, p_gacc, BSc, Dc, Dc, Dc, 2*Dc, Dc,
          1.f, nullptr, nullptr, 0, nullptr, 1, 1);

    // 17) t3 = t2 + sigmoid(gacc + gate_b) * upd
    gate_fuse_kernel<<<((long)BSc*Dc + 255)/256, 256>>>(p_t2, p_gacc, gate_b, p_upd, p_t3,
                                                        (long)BSc*Dc, Dc);

    // 18) h = rmsnorm(t3, ffn_norm_w) (reuse g_x)
    rmsnorm_kernel<<<BSc,256>>>(p_t3, ffn_norm_w, p_x, Dc, nullptr, Sc);

    // 19) gu = h @ gu_w^T + gu_b
    tc_nt(p_x, gu_w, p_gu, BSc, 2*HIDc, Dc, Dc, Dc, 2*HIDc,
          1.f, gu_b, nullptr, 0, nullptr, 1, 0);

    // 20) act = silu(g) * val
    silu_kernel<<<((long)BSc*HIDc + 255)/256, 256>>>(p_gu, p_act, BSc);

    // 21) out = t3 + act @ down_w^T + down_b
    tc_nt(p_act, down_w, out, BSc, Dc, HIDc, HIDc, HIDc, Dc,
          1.f, down_b, p_t3, Dc, nullptr, 1, 0);
}